// round 14
// baseline (speedup 1.0000x reference)
#include <cuda_runtime.h>
#include <cuda_bf16.h>
#include <cstdint>

// ---------------------------------------------------------------------------
// RGBLambertianRendererWithVisibility — R14
//   = R13 (SPB=32, NSTAGE=3, 1 CTA/SM, producer warp, full-TMA staging,
//     contiguous tile partition, in-kernel dtype detect)
//   + last-CTA fused finalize: blend + sRGB + re-zero inside the persistent
//     kernel (single fence+atomic per CTA at kernel end — NOT per tile).
//   Launches (L==64): [shade] only.
// ---------------------------------------------------------------------------

#define MAX_RAYS 65536
#define SPB 32
#define NSTAGE 3
#define NCW 16                         // compute warps
// stage layout (floats)
#define OFF_DIR  0
#define OFF_COL  (SPB * 192)
#define OFF_VIS  (SPB * 384)
#define OFF_NRM  (OFF_VIS + SPB * 64)
#define OFF_ALB  (OFF_NRM + SPB * 3)
#define OFF_WGT  (OFF_ALB + SPB * 3)
#define OFF_IDX  (OFF_WGT + SPB)
#define STAGE_FLOATS (OFF_IDX + SPB * 2)        // 14624 floats = 58496 B
#define SMEM_BYTES (NSTAGE * STAGE_FLOATS * 4)  // 175488 B

__device__ float        g_acc[MAX_RAYS * 4];    // zero at module load
__device__ int          g_idx_is64;             // generic path only
__device__ unsigned int g_done;                 // zero at module load

__global__ void detect_idx_kernel(const int* __restrict__ words, int n_words_safe) {
    int end   = n_words_safe;
    int start = end - 2048; if (start < 0) start = 0;
    int z = 0;
    for (int i = start + threadIdx.x; i < end; i += blockDim.x)
        z |= (words[i] == 0);
    int any = __syncthreads_or(z);
    if (threadIdx.x == 0) g_idx_is64 = any ? 1 : 0;
}

__device__ __forceinline__ uint32_t smem_u32(const void* p) {
    uint32_t a;
    asm("{ .reg .u64 t; cvta.to.shared.u64 t, %1; cvt.u32.u64 %0, t; }"
        : "=r"(a) : "l"(p));
    return a;
}

__device__ __forceinline__ void mbar_wait(uint32_t mbar, uint32_t parity) {
    uint32_t done;
    asm volatile(
        "{\n\t"
        ".reg .pred p;\n\t"
        "mbarrier.try_wait.parity.acquire.cta.shared::cta.b64 p, [%1], %2;\n\t"
        "selp.b32 %0, 1, 0, p;\n\t"
        "}" : "=r"(done) : "r"(mbar), "r"(parity) : "memory");
    if (!done) {
        asm volatile(
            "{\n\t"
            ".reg .pred P1;\n\t"
            "WAIT_LOOP_%=:\n\t"
            "mbarrier.try_wait.parity.acquire.cta.shared::cta.b64 P1, [%0], %1, 0x989680;\n\t"
            "@P1 bra.uni WAIT_DONE_%=;\n\t"
            "bra.uni WAIT_LOOP_%=;\n\t"
            "WAIT_DONE_%=:\n\t"
            "}" :: "r"(mbar), "r"(parity) : "memory");
    }
}

__device__ __forceinline__ void bulk_cp(uint32_t dst, const void* src,
                                        unsigned bytes, uint32_t mbar) {
    asm volatile(
        "cp.async.bulk.shared::cta.global.mbarrier::complete_tx::bytes [%0], [%1], %2, [%3];"
        :: "r"(dst), "l"(src), "r"(bytes), "r"(mbar) : "memory");
}

// --- persistent pipelined shade + fused finalize (L == 64) ------------------
__global__ __launch_bounds__(544) void shade_pipe_kernel(
        const float* __restrict__ albedos,
        const float* __restrict__ normals,
        const float* __restrict__ ldir,
        const float* __restrict__ lcol,
        const float* __restrict__ vis,
        const float* __restrict__ weights,
        const void*  __restrict__ ray_idx,
        const float* __restrict__ bg,
        float*       __restrict__ out,
        int N, int ntiles, int R, unsigned int nblocks) {
    extern __shared__ __align__(16) float smem[];
    __shared__ __align__(8) unsigned long long sm_full[NSTAGE];
    __shared__ __align__(8) unsigned long long sm_empty[NSTAGE];
    __shared__ int sm_is64;
    __shared__ int sm_last;

    int tid  = threadIdx.x;
    int warp = tid >> 5;
    int lane = tid & 31;

    if (tid == 0) {
        #pragma unroll
        for (int s = 0; s < NSTAGE; ++s) {
            asm volatile("mbarrier.init.shared.b64 [%0], 1;"
                         :: "r"(smem_u32(&sm_full[s])) : "memory");
            asm volatile("mbarrier.init.shared.b64 [%0], %1;"
                         :: "r"(smem_u32(&sm_empty[s])), "r"(NCW) : "memory");
        }
    }

    // dtype self-detection (producer warp): last 64 of the first N int32
    // words are nonzero for sorted int32 indices; int64 has zero high words.
    if (warp == NCW) {
        int end   = N;
        int start = end - 64; if (start < 0) start = 0;
        const int* words = (const int*)ray_idx;
        int z = 0;
        for (int i = start + lane; i < end; i += 32) z |= (words[i] == 0);
        unsigned any = __ballot_sync(0xFFFFFFFFu, z);
        if (lane == 0) sm_is64 = (any != 0u) ? 1 : 0;
    }
    __syncthreads();
    int is64 = sm_is64;

    // contiguous tile partition: CTA b owns tiles [t0, t0+my_tiles)
    int nb   = (int)gridDim.x;
    int bpc  = ntiles / nb;
    int rem  = ntiles - bpc * nb;
    int b    = (int)blockIdx.x;
    int t0   = b * bpc + (b < rem ? b : rem);
    int my_tiles = bpc + (b < rem ? 1 : 0);

    if (warp == NCW) {
        // ---------------- producer warp ----------------
        if (lane == 0) {
            int stage = 0, phase = 1;
            for (int j = 0; j < my_tiles; ++j) {
                mbar_wait(smem_u32(&sm_empty[stage]), (uint32_t)phase);
                asm volatile("fence.proxy.async.shared::cta;" ::: "memory");
                int tb = (t0 + j) * SPB;
                int nloc = N - tb; if (nloc > SPB) nloc = SPB;
                bool aux = (nloc % 4) == 0;

                float* stg = smem + stage * STAGE_FLOATS;
                uint32_t mb = smem_u32(&sm_full[stage]);
                unsigned db = (unsigned)nloc * 768u;
                unsigned vb = (unsigned)nloc * 256u;
                unsigned ab = aux ? ((unsigned)nloc * (12u + 12u + 4u)
                                     + (unsigned)nloc * (is64 ? 8u : 4u)) : 0u;
                asm volatile("mbarrier.arrive.expect_tx.shared.b64 _, [%0], %1;"
                             :: "r"(mb), "r"(db * 2u + vb + ab) : "memory");
                bulk_cp(smem_u32(stg + OFF_DIR), ldir + (size_t)tb * 192, db, mb);
                bulk_cp(smem_u32(stg + OFF_COL), lcol + (size_t)tb * 192, db, mb);
                bulk_cp(smem_u32(stg + OFF_VIS), vis  + (size_t)tb * 64,  vb, mb);
                if (aux) {
                    bulk_cp(smem_u32(stg + OFF_NRM), normals + (size_t)tb * 3,
                            (unsigned)nloc * 12u, mb);
                    bulk_cp(smem_u32(stg + OFF_ALB), albedos + (size_t)tb * 3,
                            (unsigned)nloc * 12u, mb);
                    bulk_cp(smem_u32(stg + OFF_WGT), weights + (size_t)tb,
                            (unsigned)nloc * 4u, mb);
                    if (is64)
                        bulk_cp(smem_u32(stg + OFF_IDX),
                                (const long long*)ray_idx + tb,
                                (unsigned)nloc * 8u, mb);
                    else
                        bulk_cp(smem_u32(stg + OFF_IDX),
                                (const int*)ray_idx + tb,
                                (unsigned)nloc * 4u, mb);
                }
                if (++stage == NSTAGE) { stage = 0; phase ^= 1; }
            }
        }
    } else {
        // ---------------- compute warps (warp 0..15) ----------------
        int half = lane >> 4;
        int sub  = lane & 15;
        int sl   = warp * 2 + half;    // local sample 0..31

        int stage = 0, phase = 0;
        for (int j = 0; j < my_tiles; ++j) {
            int base = (t0 + j) * SPB;
            int nloc = N - base; if (nloc > SPB) nloc = SPB;
            bool aux = (nloc % 4) == 0;

            mbar_wait(smem_u32(&sm_full[stage]), (uint32_t)phase);

            float* stg = smem + stage * STAGE_FLOATS;
            int s    = base + sl;
            bool live = (s < N);
            int sll  = live ? sl : 0;

            const float4* sd = (const float4*)(stg + OFF_DIR + sll * 192);
            const float4* sc = (const float4*)(stg + OFF_COL + sll * 192);
            const float4* sv = (const float4*)(stg + OFF_VIS + sll * 64);

            float4 d0 = sd[sub * 3 + 0];
            float4 d1 = sd[sub * 3 + 1];
            float4 d2 = sd[sub * 3 + 2];
            float4 c0 = sc[sub * 3 + 0];
            float4 c1 = sc[sub * 3 + 1];
            float4 c2 = sc[sub * 3 + 2];
            float4 v  = sv[sub];

            float nx, ny, nz;
            if (aux) {
                nx = stg[OFF_NRM + sll * 3 + 0];
                ny = stg[OFF_NRM + sll * 3 + 1];
                nz = stg[OFF_NRM + sll * 3 + 2];
            } else {
                int scl = live ? s : 0;
                nx = normals[scl * 3 + 0];
                ny = normals[scl * 3 + 1];
                nz = normals[scl * 3 + 2];
            }

            float w = 0.f, a0 = 0.f, a1 = 0.f, a2 = 0.f;
            int r = 0;
            if (sub == 0 && live) {
                if (aux) {
                    w  = stg[OFF_WGT + sl];
                    a0 = stg[OFF_ALB + sl * 3 + 0];
                    a1 = stg[OFF_ALB + sl * 3 + 1];
                    a2 = stg[OFF_ALB + sl * 3 + 2];
                    if (is64) r = (int)((const long long*)(stg + OFF_IDX))[sl];
                    else      r = ((const int*)(stg + OFF_IDX))[sl];
                } else {
                    w  = weights[s];
                    a0 = albedos[s * 3 + 0];
                    a1 = albedos[s * 3 + 1];
                    a2 = albedos[s * 3 + 2];
                    if (is64) r = (int)((const long long*)ray_idx)[s];
                    else      r = ((const int*)ray_idx)[s];
                }
            }

            __syncwarp();
            if (lane == 0)
                asm volatile("mbarrier.arrive.release.cta.shared::cta.b64 _, [%0];"
                             :: "r"(smem_u32(&sm_empty[stage])) : "memory");

            float t0f = fmaf(nx, d0.x, fmaf(ny, d0.y, nz * d0.z));
            float t1f = fmaf(nx, d0.w, fmaf(ny, d1.x, nz * d1.y));
            float t2f = fmaf(nx, d1.z, fmaf(ny, d1.w, nz * d2.x));
            float t3f = fmaf(nx, d2.y, fmaf(ny, d2.z, nz * d2.w));

            int cnt = (t0f > 0.f) + (t1f > 0.f) + (t2f > 0.f) + (t3f > 0.f);

            t0f = fminf(fmaxf(t0f, 0.f), 1.f) * v.x;
            t1f = fminf(fmaxf(t1f, 0.f), 1.f) * v.y;
            t2f = fminf(fmaxf(t2f, 0.f), 1.f) * v.z;
            t3f = fminf(fmaxf(t3f, 0.f), 1.f) * v.w;

            float s0 = fmaf(t0f, c0.x, fmaf(t1f, c0.w, fmaf(t2f, c1.z, t3f * c2.y)));
            float s1 = fmaf(t0f, c0.y, fmaf(t1f, c1.x, fmaf(t2f, c1.w, t3f * c2.z)));
            float s2 = fmaf(t0f, c0.z, fmaf(t1f, c1.y, fmaf(t2f, c2.x, t3f * c2.w)));

            #pragma unroll
            for (int off = 8; off; off >>= 1) {
                s0  += __shfl_xor_sync(0xFFFFFFFFu, s0,  off);
                s1  += __shfl_xor_sync(0xFFFFFFFFu, s1,  off);
                s2  += __shfl_xor_sync(0xFFFFFFFFu, s2,  off);
                cnt += __shfl_xor_sync(0xFFFFFFFFu, cnt, off);
            }

            if (sub == 0 && live) {
                float c   = (cnt > 0) ? (float)cnt : 1.0f;
                float inv = 1.0f / c;
                atomicAdd(&g_acc[r * 4 + 0], w * a0 * s0 * inv);
                atomicAdd(&g_acc[r * 4 + 1], w * a1 * s1 * inv);
                atomicAdd(&g_acc[r * 4 + 2], w * a2 * s2 * inv);
                atomicAdd(&g_acc[r * 4 + 3], w);
            }

            if (++stage == NSTAGE) { stage = 0; phase ^= 1; }
        }
    }

    // ---- kernel-end epilogue: last CTA finalizes --------------------------
    __syncthreads();                       // all 17 warps of this CTA done
    if (tid == 0) {
        __threadfence();                   // make this CTA's atomics visible
        unsigned int old = atomicAdd(&g_done, 1u);
        sm_last = (old == nblocks - 1u) ? 1 : 0;
    }
    __syncthreads();
    if (sm_last) {
        __threadfence();                   // acquire: all CTAs' atomics visible
        for (int r = tid; r < R; r += 544) {
            float aw = __ldcg(&g_acc[r * 4 + 3]);
            float x0 = __ldcg(&g_acc[r * 4 + 0]);
            float x1 = __ldcg(&g_acc[r * 4 + 1]);
            float x2 = __ldcg(&g_acc[r * 4 + 2]);
            float one_m = 1.0f - aw;
            float xr[3] = { x0 + bg[r * 3 + 0] * one_m,
                            x1 + bg[r * 3 + 1] * one_m,
                            x2 + bg[r * 3 + 2] * one_m };
            #pragma unroll
            for (int c = 0; c < 3; ++c) {
                float x = xr[c];
                float safe = fmaxf(x, 1e-8f);
                float y = (x <= 0.0031308f)
                        ? (12.92f * x)
                        : (1.055f * __powf(safe, 1.0f / 2.4f) - 0.055f);
                out[r * 3 + c] = y;
            }
            g_acc[r * 4 + 0] = 0.0f;       // re-zero for next call
            g_acc[r * 4 + 1] = 0.0f;
            g_acc[r * 4 + 2] = 0.0f;
            g_acc[r * 4 + 3] = 0.0f;
        }
        __syncthreads();
        if (tid == 0) {
            __threadfence();
            g_done = 0;                    // reset counter for next call
        }
    }
}

// standalone finalize for the generic (L != 64) path
__global__ void finalize_kernel(const float* __restrict__ bg,
                                float* __restrict__ out, int R) {
    int r = blockIdx.x * blockDim.x + threadIdx.x;
    if (r >= R) return;
    float aw = g_acc[r * 4 + 3];
    float x0 = g_acc[r * 4 + 0];
    float x1 = g_acc[r * 4 + 1];
    float x2 = g_acc[r * 4 + 2];
    float one_m = 1.0f - aw;
    float xr[3] = { x0 + bg[r * 3 + 0] * one_m,
                    x1 + bg[r * 3 + 1] * one_m,
                    x2 + bg[r * 3 + 2] * one_m };
    #pragma unroll
    for (int c = 0; c < 3; ++c) {
        float x = xr[c];
        float safe = fmaxf(x, 1e-8f);
        float y = (x <= 0.0031308f) ? (12.92f * x)
                                    : (1.055f * __powf(safe, 1.0f / 2.4f) - 0.055f);
        out[r * 3 + c] = y;
    }
    g_acc[r * 4 + 0] = 0.0f;
    g_acc[r * 4 + 1] = 0.0f;
    g_acc[r * 4 + 2] = 0.0f;
    g_acc[r * 4 + 3] = 0.0f;
}

// Fallback for L != 64
__global__ void shade_kernel_generic(
        const float* __restrict__ albedos,
        const float* __restrict__ normals,
        const float* __restrict__ ldir,
        const float* __restrict__ lcol,
        const float* __restrict__ vis,
        const float* __restrict__ weights,
        const void*  __restrict__ ray_idx,
        int N, int L) {
    int gwarp = (blockIdx.x * blockDim.x + threadIdx.x) >> 5;
    int lane  = threadIdx.x & 31;
    if (gwarp >= N) return;
    float nx = normals[gwarp * 3 + 0];
    float ny = normals[gwarp * 3 + 1];
    float nz = normals[gwarp * 3 + 2];
    const float* ldp = ldir + (size_t)gwarp * L * 3;
    const float* lcp = lcol + (size_t)gwarp * L * 3;
    const float* vp  = vis  + (size_t)gwarp * L;
    float s0 = 0.f, s1 = 0.f, s2 = 0.f;
    int cnt = 0;
    for (int j = lane; j < L; j += 32) {
        float dx = ldp[j * 3 + 0], dy = ldp[j * 3 + 1], dz = ldp[j * 3 + 2];
        float d  = fmaf(nx, dx, fmaf(ny, dy, nz * dz));
        cnt += (d > 0.f) ? 1 : 0;
        d = fminf(fmaxf(d, 0.f), 1.f);
        float dv = d * vp[j];
        s0 = fmaf(dv, lcp[j * 3 + 0], s0);
        s1 = fmaf(dv, lcp[j * 3 + 1], s1);
        s2 = fmaf(dv, lcp[j * 3 + 2], s2);
    }
    #pragma unroll
    for (int off = 16; off; off >>= 1) {
        s0  += __shfl_xor_sync(0xFFFFFFFFu, s0,  off);
        s1  += __shfl_xor_sync(0xFFFFFFFFu, s1,  off);
        s2  += __shfl_xor_sync(0xFFFFFFFFu, s2,  off);
        cnt += __shfl_xor_sync(0xFFFFFFFFu, cnt, off);
    }
    if (lane == 0) {
        float c   = (cnt > 0) ? (float)cnt : 1.0f;
        float inv = 1.0f / c;
        float w   = weights[gwarp];
        int r;
        if (g_idx_is64) r = (int)((const long long*)ray_idx)[gwarp];
        else            r = ((const int*)ray_idx)[gwarp];
        atomicAdd(&g_acc[r * 4 + 0], w * albedos[gwarp * 3 + 0] * s0 * inv);
        atomicAdd(&g_acc[r * 4 + 1], w * albedos[gwarp * 3 + 1] * s1 * inv);
        atomicAdd(&g_acc[r * 4 + 2], w * albedos[gwarp * 3 + 2] * s2 * inv);
        atomicAdd(&g_acc[r * 4 + 3], w);
    }
}

extern "C" void kernel_launch(void* const* d_in, const int* in_sizes, int n_in,
                              void* d_out, int out_size) {
    const float* albedos = (const float*)d_in[0];
    const float* normals = (const float*)d_in[1];
    const float* ldir    = (const float*)d_in[2];
    const float* lcol    = (const float*)d_in[3];
    const float* vis     = (const float*)d_in[4];
    const float* bg      = (const float*)d_in[5];
    const float* weights = (const float*)d_in[6];
    const void*  ray_idx = (const void*) d_in[7];
    float* out = (float*)d_out;

    int N = in_sizes[0] / 3;
    int L = (N > 0) ? in_sizes[2] / (N * 3) : 1;
    int R = out_size / 3;
    if (R > MAX_RAYS) R = MAX_RAYS;

    // g_acc/g_done zero at module load; the fused epilogue (or finalize
    // kernel on the generic path) re-zeros them at the end of every call.
    if (L == 64) {
        static int smem_set = 0;
        if (!smem_set) {
            cudaFuncSetAttribute(shade_pipe_kernel,
                                 cudaFuncAttributeMaxDynamicSharedMemorySize,
                                 SMEM_BYTES);
            smem_set = 1;
        }
        int ntiles = (N + SPB - 1) / SPB;
        int grid = 148;                 // 1 CTA per SM
        if (grid > ntiles) grid = ntiles;
        shade_pipe_kernel<<<grid, 544, SMEM_BYTES>>>(
            albedos, normals, ldir, lcol, vis, weights, ray_idx,
            bg, out, N, ntiles, R, (unsigned int)grid);
    } else {
        detect_idx_kernel<<<1, 1024>>>((const int*)ray_idx, in_sizes[7]);
        int blocks = (N + 7) / 8;
        shade_kernel_generic<<<blocks, 256>>>(
            albedos, normals, ldir, lcol, vis, weights, ray_idx, N, L);
        finalize_kernel<<<(R + 255) / 256, 256>>>(bg, out, R);
    }
}

// round 15
// speedup vs baseline: 1.1969x; 1.1969x over previous
#include <cuda_runtime.h>
#include <cuda_bf16.h>
#include <cstdint>

// ---------------------------------------------------------------------------
// RGBLambertianRendererWithVisibility — R15 (= R12, measured best: 152.0us)
//   Persistent TMA pipeline: SPB=32, NSTAGE=3 (175KB smem), 1 CTA/SM,
//   warp-specialized producer, full-TMA staging of ALL per-sample data,
//   contiguous per-CTA tile partition, __powf finalize(+zero).
//   Launches: [detect, shade, finalize].
// ---------------------------------------------------------------------------

#define MAX_RAYS 65536
#define SPB 32
#define NSTAGE 3
#define NCW 16                         // compute warps
// stage layout (floats)
#define OFF_DIR  0
#define OFF_COL  (SPB * 192)
#define OFF_VIS  (SPB * 384)
#define OFF_NRM  (OFF_VIS + SPB * 64)
#define OFF_ALB  (OFF_NRM + SPB * 3)
#define OFF_WGT  (OFF_ALB + SPB * 3)
#define OFF_IDX  (OFF_WGT + SPB)
#define STAGE_FLOATS (OFF_IDX + SPB * 2)        // 14624 floats = 58496 B
#define SMEM_BYTES (NSTAGE * STAGE_FLOATS * 4)  // 175488 B

__device__ float g_acc[MAX_RAYS * 4];
__device__ int   g_idx_is64;

// int32 vs int64 ray_indices: inspect last 2048 of the first N int32 words
// (in-bounds for both layouts). Sorted nonneg indices are nonzero there for
// int32; int64 interleaves zero high words.
__global__ void detect_idx_kernel(const int* __restrict__ words, int n_words_safe) {
    int end   = n_words_safe;
    int start = end - 2048; if (start < 0) start = 0;
    int z = 0;
    for (int i = start + threadIdx.x; i < end; i += blockDim.x)
        z |= (words[i] == 0);
    int any = __syncthreads_or(z);
    if (threadIdx.x == 0) g_idx_is64 = any ? 1 : 0;
}

__device__ __forceinline__ uint32_t smem_u32(const void* p) {
    uint32_t a;
    asm("{ .reg .u64 t; cvta.to.shared.u64 t, %1; cvt.u32.u64 %0, t; }"
        : "=r"(a) : "l"(p));
    return a;
}

__device__ __forceinline__ void mbar_wait(uint32_t mbar, uint32_t parity) {
    uint32_t done;
    asm volatile(
        "{\n\t"
        ".reg .pred p;\n\t"
        "mbarrier.try_wait.parity.acquire.cta.shared::cta.b64 p, [%1], %2;\n\t"
        "selp.b32 %0, 1, 0, p;\n\t"
        "}" : "=r"(done) : "r"(mbar), "r"(parity) : "memory");
    if (!done) {
        asm volatile(
            "{\n\t"
            ".reg .pred P1;\n\t"
            "WAIT_LOOP_%=:\n\t"
            "mbarrier.try_wait.parity.acquire.cta.shared::cta.b64 P1, [%0], %1, 0x989680;\n\t"
            "@P1 bra.uni WAIT_DONE_%=;\n\t"
            "bra.uni WAIT_LOOP_%=;\n\t"
            "WAIT_DONE_%=:\n\t"
            "}" :: "r"(mbar), "r"(parity) : "memory");
    }
}

__device__ __forceinline__ void bulk_cp(uint32_t dst, const void* src,
                                        unsigned bytes, uint32_t mbar) {
    asm volatile(
        "cp.async.bulk.shared::cta.global.mbarrier::complete_tx::bytes [%0], [%1], %2, [%3];"
        :: "r"(dst), "l"(src), "r"(bytes), "r"(mbar) : "memory");
}

// --- persistent pipelined shade (L == 64) -----------------------------------
__global__ __launch_bounds__(544) void shade_pipe_kernel(
        const float* __restrict__ albedos,
        const float* __restrict__ normals,
        const float* __restrict__ ldir,
        const float* __restrict__ lcol,
        const float* __restrict__ vis,
        const float* __restrict__ weights,
        const void*  __restrict__ ray_idx,
        int N, int ntiles) {
    extern __shared__ __align__(16) float smem[];
    __shared__ __align__(8) unsigned long long sm_full[NSTAGE];
    __shared__ __align__(8) unsigned long long sm_empty[NSTAGE];

    int tid  = threadIdx.x;
    int warp = tid >> 5;
    int lane = tid & 31;

    if (tid == 0) {
        #pragma unroll
        for (int s = 0; s < NSTAGE; ++s) {
            asm volatile("mbarrier.init.shared.b64 [%0], 1;"
                         :: "r"(smem_u32(&sm_full[s])) : "memory");
            asm volatile("mbarrier.init.shared.b64 [%0], %1;"
                         :: "r"(smem_u32(&sm_empty[s])), "r"(NCW) : "memory");
        }
    }
    __syncthreads();

    // contiguous tile partition: CTA b owns tiles [t0, t0+cnt)
    int nb   = (int)gridDim.x;
    int bpc  = ntiles / nb;            // base tiles per CTA
    int rem  = ntiles - bpc * nb;      // first `rem` CTAs get one extra
    int b    = (int)blockIdx.x;
    int t0   = b * bpc + (b < rem ? b : rem);
    int my_tiles = bpc + (b < rem ? 1 : 0);
    if (my_tiles == 0) return;

    int is64 = g_idx_is64;

    if (warp == NCW) {
        // ---------------- producer warp ----------------
        if (lane == 0) {
            int stage = 0, phase = 1;
            for (int j = 0; j < my_tiles; ++j) {
                mbar_wait(smem_u32(&sm_empty[stage]), (uint32_t)phase);
                asm volatile("fence.proxy.async.shared::cta;" ::: "memory");
                int tb = (t0 + j) * SPB;
                int nloc = N - tb; if (nloc > SPB) nloc = SPB;
                bool aux = (nloc % 4) == 0;

                float* stg = smem + stage * STAGE_FLOATS;
                uint32_t mb = smem_u32(&sm_full[stage]);
                unsigned db = (unsigned)nloc * 768u;
                unsigned vb = (unsigned)nloc * 256u;
                unsigned ab = aux ? ((unsigned)nloc * (12u + 12u + 4u)
                                     + (unsigned)nloc * (is64 ? 8u : 4u)) : 0u;
                asm volatile("mbarrier.arrive.expect_tx.shared.b64 _, [%0], %1;"
                             :: "r"(mb), "r"(db * 2u + vb + ab) : "memory");
                bulk_cp(smem_u32(stg + OFF_DIR), ldir + (size_t)tb * 192, db, mb);
                bulk_cp(smem_u32(stg + OFF_COL), lcol + (size_t)tb * 192, db, mb);
                bulk_cp(smem_u32(stg + OFF_VIS), vis  + (size_t)tb * 64,  vb, mb);
                if (aux) {
                    bulk_cp(smem_u32(stg + OFF_NRM), normals + (size_t)tb * 3,
                            (unsigned)nloc * 12u, mb);
                    bulk_cp(smem_u32(stg + OFF_ALB), albedos + (size_t)tb * 3,
                            (unsigned)nloc * 12u, mb);
                    bulk_cp(smem_u32(stg + OFF_WGT), weights + (size_t)tb,
                            (unsigned)nloc * 4u, mb);
                    if (is64)
                        bulk_cp(smem_u32(stg + OFF_IDX),
                                (const long long*)ray_idx + tb,
                                (unsigned)nloc * 8u, mb);
                    else
                        bulk_cp(smem_u32(stg + OFF_IDX),
                                (const int*)ray_idx + tb,
                                (unsigned)nloc * 4u, mb);
                }
                if (++stage == NSTAGE) { stage = 0; phase ^= 1; }
            }
        }
        return;
    }

    // ---------------- compute warps (warp 0..15) ----------------
    int half = lane >> 4;
    int sub  = lane & 15;
    int sl   = warp * 2 + half;        // local sample 0..31

    int stage = 0, phase = 0;
    for (int j = 0; j < my_tiles; ++j) {
        int base = (t0 + j) * SPB;
        int nloc = N - base; if (nloc > SPB) nloc = SPB;
        bool aux = (nloc % 4) == 0;

        mbar_wait(smem_u32(&sm_full[stage]), (uint32_t)phase);

        float* stg = smem + stage * STAGE_FLOATS;
        int s    = base + sl;
        bool live = (s < N);
        int sll  = live ? sl : 0;

        const float4* sd = (const float4*)(stg + OFF_DIR + sll * 192);
        const float4* sc = (const float4*)(stg + OFF_COL + sll * 192);
        const float4* sv = (const float4*)(stg + OFF_VIS + sll * 64);

        float4 d0 = sd[sub * 3 + 0];
        float4 d1 = sd[sub * 3 + 1];
        float4 d2 = sd[sub * 3 + 2];
        float4 c0 = sc[sub * 3 + 0];
        float4 c1 = sc[sub * 3 + 1];
        float4 c2 = sc[sub * 3 + 2];
        float4 v  = sv[sub];

        float nx, ny, nz;
        if (aux) {
            nx = stg[OFF_NRM + sll * 3 + 0];
            ny = stg[OFF_NRM + sll * 3 + 1];
            nz = stg[OFF_NRM + sll * 3 + 2];
        } else {
            int scl = live ? s : 0;
            nx = normals[scl * 3 + 0];
            ny = normals[scl * 3 + 1];
            nz = normals[scl * 3 + 2];
        }

        float w = 0.f, a0 = 0.f, a1 = 0.f, a2 = 0.f;
        int r = 0;
        if (sub == 0 && live) {
            if (aux) {
                w  = stg[OFF_WGT + sl];
                a0 = stg[OFF_ALB + sl * 3 + 0];
                a1 = stg[OFF_ALB + sl * 3 + 1];
                a2 = stg[OFF_ALB + sl * 3 + 2];
                if (is64) r = (int)((const long long*)(stg + OFF_IDX))[sl];
                else      r = ((const int*)(stg + OFF_IDX))[sl];
            } else {
                w  = weights[s];
                a0 = albedos[s * 3 + 0];
                a1 = albedos[s * 3 + 1];
                a2 = albedos[s * 3 + 2];
                if (is64) r = (int)((const long long*)ray_idx)[s];
                else      r = ((const int*)ray_idx)[s];
            }
        }

        // all stage reads done -> release stage (one arrive per warp)
        __syncwarp();
        if (lane == 0)
            asm volatile("mbarrier.arrive.release.cta.shared::cta.b64 _, [%0];"
                         :: "r"(smem_u32(&sm_empty[stage])) : "memory");

        float t0f = fmaf(nx, d0.x, fmaf(ny, d0.y, nz * d0.z));
        float t1f = fmaf(nx, d0.w, fmaf(ny, d1.x, nz * d1.y));
        float t2f = fmaf(nx, d1.z, fmaf(ny, d1.w, nz * d2.x));
        float t3f = fmaf(nx, d2.y, fmaf(ny, d2.z, nz * d2.w));

        int cnt = (t0f > 0.f) + (t1f > 0.f) + (t2f > 0.f) + (t3f > 0.f);

        t0f = fminf(fmaxf(t0f, 0.f), 1.f) * v.x;
        t1f = fminf(fmaxf(t1f, 0.f), 1.f) * v.y;
        t2f = fminf(fmaxf(t2f, 0.f), 1.f) * v.z;
        t3f = fminf(fmaxf(t3f, 0.f), 1.f) * v.w;

        float s0 = fmaf(t0f, c0.x, fmaf(t1f, c0.w, fmaf(t2f, c1.z, t3f * c2.y)));
        float s1 = fmaf(t0f, c0.y, fmaf(t1f, c1.x, fmaf(t2f, c1.w, t3f * c2.z)));
        float s2 = fmaf(t0f, c0.z, fmaf(t1f, c1.y, fmaf(t2f, c2.x, t3f * c2.w)));

        #pragma unroll
        for (int off = 8; off; off >>= 1) {
            s0  += __shfl_xor_sync(0xFFFFFFFFu, s0,  off);
            s1  += __shfl_xor_sync(0xFFFFFFFFu, s1,  off);
            s2  += __shfl_xor_sync(0xFFFFFFFFu, s2,  off);
            cnt += __shfl_xor_sync(0xFFFFFFFFu, cnt, off);
        }

        if (sub == 0 && live) {
            float c   = (cnt > 0) ? (float)cnt : 1.0f;
            float inv = 1.0f / c;
            atomicAdd(&g_acc[r * 4 + 0], w * a0 * s0 * inv);
            atomicAdd(&g_acc[r * 4 + 1], w * a1 * s1 * inv);
            atomicAdd(&g_acc[r * 4 + 2], w * a2 * s2 * inv);
            atomicAdd(&g_acc[r * 4 + 3], w);
        }

        if (++stage == NSTAGE) { stage = 0; phase ^= 1; }
    }
}

// finalize: blend + sRGB, then zero g_acc for the NEXT call.
__global__ void finalize_kernel(const float* __restrict__ bg,
                                float* __restrict__ out, int R) {
    int r = blockIdx.x * blockDim.x + threadIdx.x;
    if (r >= R) return;
    float aw = g_acc[r * 4 + 3];
    float x0 = g_acc[r * 4 + 0];
    float x1 = g_acc[r * 4 + 1];
    float x2 = g_acc[r * 4 + 2];
    float one_m = 1.0f - aw;
    float xr[3] = { x0 + bg[r * 3 + 0] * one_m,
                    x1 + bg[r * 3 + 1] * one_m,
                    x2 + bg[r * 3 + 2] * one_m };
    #pragma unroll
    for (int c = 0; c < 3; ++c) {
        float x = xr[c];
        float safe = fmaxf(x, 1e-8f);
        float y = (x <= 0.0031308f) ? (12.92f * x)
                                    : (1.055f * __powf(safe, 1.0f / 2.4f) - 0.055f);
        out[r * 3 + c] = y;
    }
    g_acc[r * 4 + 0] = 0.0f;
    g_acc[r * 4 + 1] = 0.0f;
    g_acc[r * 4 + 2] = 0.0f;
    g_acc[r * 4 + 3] = 0.0f;
}

// Fallback for L != 64
__global__ void shade_kernel_generic(
        const float* __restrict__ albedos,
        const float* __restrict__ normals,
        const float* __restrict__ ldir,
        const float* __restrict__ lcol,
        const float* __restrict__ vis,
        const float* __restrict__ weights,
        const void*  __restrict__ ray_idx,
        int N, int L) {
    int gwarp = (blockIdx.x * blockDim.x + threadIdx.x) >> 5;
    int lane  = threadIdx.x & 31;
    if (gwarp >= N) return;
    float nx = normals[gwarp * 3 + 0];
    float ny = normals[gwarp * 3 + 1];
    float nz = normals[gwarp * 3 + 2];
    const float* ldp = ldir + (size_t)gwarp * L * 3;
    const float* lcp = lcol + (size_t)gwarp * L * 3;
    const float* vp  = vis  + (size_t)gwarp * L;
    float s0 = 0.f, s1 = 0.f, s2 = 0.f;
    int cnt = 0;
    for (int j = lane; j < L; j += 32) {
        float dx = ldp[j * 3 + 0], dy = ldp[j * 3 + 1], dz = ldp[j * 3 + 2];
        float d  = fmaf(nx, dx, fmaf(ny, dy, nz * dz));
        cnt += (d > 0.f) ? 1 : 0;
        d = fminf(fmaxf(d, 0.f), 1.f);
        float dv = d * vp[j];
        s0 = fmaf(dv, lcp[j * 3 + 0], s0);
        s1 = fmaf(dv, lcp[j * 3 + 1], s1);
        s2 = fmaf(dv, lcp[j * 3 + 2], s2);
    }
    #pragma unroll
    for (int off = 16; off; off >>= 1) {
        s0  += __shfl_xor_sync(0xFFFFFFFFu, s0,  off);
        s1  += __shfl_xor_sync(0xFFFFFFFFu, s1,  off);
        s2  += __shfl_xor_sync(0xFFFFFFFFu, s2,  off);
        cnt += __shfl_xor_sync(0xFFFFFFFFu, cnt, off);
    }
    if (lane == 0) {
        float c   = (cnt > 0) ? (float)cnt : 1.0f;
        float inv = 1.0f / c;
        float w   = weights[gwarp];
        int r;
        if (g_idx_is64) r = (int)((const long long*)ray_idx)[gwarp];
        else            r = ((const int*)ray_idx)[gwarp];
        atomicAdd(&g_acc[r * 4 + 0], w * albedos[gwarp * 3 + 0] * s0 * inv);
        atomicAdd(&g_acc[r * 4 + 1], w * albedos[gwarp * 3 + 1] * s1 * inv);
        atomicAdd(&g_acc[r * 4 + 2], w * albedos[gwarp * 3 + 2] * s2 * inv);
        atomicAdd(&g_acc[r * 4 + 3], w);
    }
}

extern "C" void kernel_launch(void* const* d_in, const int* in_sizes, int n_in,
                              void* d_out, int out_size) {
    const float* albedos = (const float*)d_in[0];
    const float* normals = (const float*)d_in[1];
    const float* ldir    = (const float*)d_in[2];
    const float* lcol    = (const float*)d_in[3];
    const float* vis     = (const float*)d_in[4];
    const float* bg      = (const float*)d_in[5];
    const float* weights = (const float*)d_in[6];
    const void*  ray_idx = (const void*) d_in[7];
    float* out = (float*)d_out;

    int N = in_sizes[0] / 3;
    int L = (N > 0) ? in_sizes[2] / (N * 3) : 1;
    int R = out_size / 3;
    if (R > MAX_RAYS) R = MAX_RAYS;

    // g_acc zero at load (call 1); finalize re-zeros it each call.
    detect_idx_kernel<<<1, 1024>>>((const int*)ray_idx, in_sizes[7]);

    if (L == 64) {
        static int smem_set = 0;
        if (!smem_set) {
            cudaFuncSetAttribute(shade_pipe_kernel,
                                 cudaFuncAttributeMaxDynamicSharedMemorySize,
                                 SMEM_BYTES);
            smem_set = 1;
        }
        int ntiles = (N + SPB - 1) / SPB;
        int grid = 148;                 // 1 CTA per SM
        if (grid > ntiles) grid = ntiles;
        shade_pipe_kernel<<<grid, 544, SMEM_BYTES>>>(
            albedos, normals, ldir, lcol, vis, weights, ray_idx, N, ntiles);
    } else {
        int blocks = (N + 7) / 8;
        shade_kernel_generic<<<blocks, 256>>>(
            albedos, normals, ldir, lcol, vis, weights, ray_idx, N, L);
    }

    finalize_kernel<<<(R + 255) / 256, 256>>>(bg, out, R);
}

// round 16
// speedup vs baseline: 1.2004x; 1.0029x over previous
#include <cuda_runtime.h>
#include <cuda_bf16.h>
#include <cstdint>

// ---------------------------------------------------------------------------
// RGBLambertianRendererWithVisibility — FINAL (= R12, measured best: 152.0us)
//   Persistent TMA pipeline: SPB=32, NSTAGE=3 (175KB smem), 1 CTA/SM,
//   warp-specialized producer, full-TMA staging of ALL per-sample data,
//   contiguous per-CTA tile partition, __powf finalize(+zero).
//   Launches: [detect, shade, finalize].
// ---------------------------------------------------------------------------

#define MAX_RAYS 65536
#define SPB 32
#define NSTAGE 3
#define NCW 16                         // compute warps
// stage layout (floats)
#define OFF_DIR  0
#define OFF_COL  (SPB * 192)
#define OFF_VIS  (SPB * 384)
#define OFF_NRM  (OFF_VIS + SPB * 64)
#define OFF_ALB  (OFF_NRM + SPB * 3)
#define OFF_WGT  (OFF_ALB + SPB * 3)
#define OFF_IDX  (OFF_WGT + SPB)
#define STAGE_FLOATS (OFF_IDX + SPB * 2)        // 14624 floats = 58496 B
#define SMEM_BYTES (NSTAGE * STAGE_FLOATS * 4)  // 175488 B

__device__ float g_acc[MAX_RAYS * 4];
__device__ int   g_idx_is64;

// int32 vs int64 ray_indices: inspect last 2048 of the first N int32 words
// (in-bounds for both layouts). Sorted nonneg indices are nonzero there for
// int32; int64 interleaves zero high words.
__global__ void detect_idx_kernel(const int* __restrict__ words, int n_words_safe) {
    int end   = n_words_safe;
    int start = end - 2048; if (start < 0) start = 0;
    int z = 0;
    for (int i = start + threadIdx.x; i < end; i += blockDim.x)
        z |= (words[i] == 0);
    int any = __syncthreads_or(z);
    if (threadIdx.x == 0) g_idx_is64 = any ? 1 : 0;
}

__device__ __forceinline__ uint32_t smem_u32(const void* p) {
    uint32_t a;
    asm("{ .reg .u64 t; cvta.to.shared.u64 t, %1; cvt.u32.u64 %0, t; }"
        : "=r"(a) : "l"(p));
    return a;
}

__device__ __forceinline__ void mbar_wait(uint32_t mbar, uint32_t parity) {
    uint32_t done;
    asm volatile(
        "{\n\t"
        ".reg .pred p;\n\t"
        "mbarrier.try_wait.parity.acquire.cta.shared::cta.b64 p, [%1], %2;\n\t"
        "selp.b32 %0, 1, 0, p;\n\t"
        "}" : "=r"(done) : "r"(mbar), "r"(parity) : "memory");
    if (!done) {
        asm volatile(
            "{\n\t"
            ".reg .pred P1;\n\t"
            "WAIT_LOOP_%=:\n\t"
            "mbarrier.try_wait.parity.acquire.cta.shared::cta.b64 P1, [%0], %1, 0x989680;\n\t"
            "@P1 bra.uni WAIT_DONE_%=;\n\t"
            "bra.uni WAIT_LOOP_%=;\n\t"
            "WAIT_DONE_%=:\n\t"
            "}" :: "r"(mbar), "r"(parity) : "memory");
    }
}

__device__ __forceinline__ void bulk_cp(uint32_t dst, const void* src,
                                        unsigned bytes, uint32_t mbar) {
    asm volatile(
        "cp.async.bulk.shared::cta.global.mbarrier::complete_tx::bytes [%0], [%1], %2, [%3];"
        :: "r"(dst), "l"(src), "r"(bytes), "r"(mbar) : "memory");
}

// --- persistent pipelined shade (L == 64) -----------------------------------
__global__ __launch_bounds__(544) void shade_pipe_kernel(
        const float* __restrict__ albedos,
        const float* __restrict__ normals,
        const float* __restrict__ ldir,
        const float* __restrict__ lcol,
        const float* __restrict__ vis,
        const float* __restrict__ weights,
        const void*  __restrict__ ray_idx,
        int N, int ntiles) {
    extern __shared__ __align__(16) float smem[];
    __shared__ __align__(8) unsigned long long sm_full[NSTAGE];
    __shared__ __align__(8) unsigned long long sm_empty[NSTAGE];

    int tid  = threadIdx.x;
    int warp = tid >> 5;
    int lane = tid & 31;

    if (tid == 0) {
        #pragma unroll
        for (int s = 0; s < NSTAGE; ++s) {
            asm volatile("mbarrier.init.shared.b64 [%0], 1;"
                         :: "r"(smem_u32(&sm_full[s])) : "memory");
            asm volatile("mbarrier.init.shared.b64 [%0], %1;"
                         :: "r"(smem_u32(&sm_empty[s])), "r"(NCW) : "memory");
        }
    }
    __syncthreads();

    // contiguous tile partition: CTA b owns tiles [t0, t0+cnt)
    int nb   = (int)gridDim.x;
    int bpc  = ntiles / nb;            // base tiles per CTA
    int rem  = ntiles - bpc * nb;      // first `rem` CTAs get one extra
    int b    = (int)blockIdx.x;
    int t0   = b * bpc + (b < rem ? b : rem);
    int my_tiles = bpc + (b < rem ? 1 : 0);
    if (my_tiles == 0) return;

    int is64 = g_idx_is64;

    if (warp == NCW) {
        // ---------------- producer warp ----------------
        if (lane == 0) {
            int stage = 0, phase = 1;
            for (int j = 0; j < my_tiles; ++j) {
                mbar_wait(smem_u32(&sm_empty[stage]), (uint32_t)phase);
                asm volatile("fence.proxy.async.shared::cta;" ::: "memory");
                int tb = (t0 + j) * SPB;
                int nloc = N - tb; if (nloc > SPB) nloc = SPB;
                bool aux = (nloc % 4) == 0;

                float* stg = smem + stage * STAGE_FLOATS;
                uint32_t mb = smem_u32(&sm_full[stage]);
                unsigned db = (unsigned)nloc * 768u;
                unsigned vb = (unsigned)nloc * 256u;
                unsigned ab = aux ? ((unsigned)nloc * (12u + 12u + 4u)
                                     + (unsigned)nloc * (is64 ? 8u : 4u)) : 0u;
                asm volatile("mbarrier.arrive.expect_tx.shared.b64 _, [%0], %1;"
                             :: "r"(mb), "r"(db * 2u + vb + ab) : "memory");
                bulk_cp(smem_u32(stg + OFF_DIR), ldir + (size_t)tb * 192, db, mb);
                bulk_cp(smem_u32(stg + OFF_COL), lcol + (size_t)tb * 192, db, mb);
                bulk_cp(smem_u32(stg + OFF_VIS), vis  + (size_t)tb * 64,  vb, mb);
                if (aux) {
                    bulk_cp(smem_u32(stg + OFF_NRM), normals + (size_t)tb * 3,
                            (unsigned)nloc * 12u, mb);
                    bulk_cp(smem_u32(stg + OFF_ALB), albedos + (size_t)tb * 3,
                            (unsigned)nloc * 12u, mb);
                    bulk_cp(smem_u32(stg + OFF_WGT), weights + (size_t)tb,
                            (unsigned)nloc * 4u, mb);
                    if (is64)
                        bulk_cp(smem_u32(stg + OFF_IDX),
                                (const long long*)ray_idx + tb,
                                (unsigned)nloc * 8u, mb);
                    else
                        bulk_cp(smem_u32(stg + OFF_IDX),
                                (const int*)ray_idx + tb,
                                (unsigned)nloc * 4u, mb);
                }
                if (++stage == NSTAGE) { stage = 0; phase ^= 1; }
            }
        }
        return;
    }

    // ---------------- compute warps (warp 0..15) ----------------
    int half = lane >> 4;
    int sub  = lane & 15;
    int sl   = warp * 2 + half;        // local sample 0..31

    int stage = 0, phase = 0;
    for (int j = 0; j < my_tiles; ++j) {
        int base = (t0 + j) * SPB;
        int nloc = N - base; if (nloc > SPB) nloc = SPB;
        bool aux = (nloc % 4) == 0;

        mbar_wait(smem_u32(&sm_full[stage]), (uint32_t)phase);

        float* stg = smem + stage * STAGE_FLOATS;
        int s    = base + sl;
        bool live = (s < N);
        int sll  = live ? sl : 0;

        const float4* sd = (const float4*)(stg + OFF_DIR + sll * 192);
        const float4* sc = (const float4*)(stg + OFF_COL + sll * 192);
        const float4* sv = (const float4*)(stg + OFF_VIS + sll * 64);

        float4 d0 = sd[sub * 3 + 0];
        float4 d1 = sd[sub * 3 + 1];
        float4 d2 = sd[sub * 3 + 2];
        float4 c0 = sc[sub * 3 + 0];
        float4 c1 = sc[sub * 3 + 1];
        float4 c2 = sc[sub * 3 + 2];
        float4 v  = sv[sub];

        float nx, ny, nz;
        if (aux) {
            nx = stg[OFF_NRM + sll * 3 + 0];
            ny = stg[OFF_NRM + sll * 3 + 1];
            nz = stg[OFF_NRM + sll * 3 + 2];
        } else {
            int scl = live ? s : 0;
            nx = normals[scl * 3 + 0];
            ny = normals[scl * 3 + 1];
            nz = normals[scl * 3 + 2];
        }

        float w = 0.f, a0 = 0.f, a1 = 0.f, a2 = 0.f;
        int r = 0;
        if (sub == 0 && live) {
            if (aux) {
                w  = stg[OFF_WGT + sl];
                a0 = stg[OFF_ALB + sl * 3 + 0];
                a1 = stg[OFF_ALB + sl * 3 + 1];
                a2 = stg[OFF_ALB + sl * 3 + 2];
                if (is64) r = (int)((const long long*)(stg + OFF_IDX))[sl];
                else      r = ((const int*)(stg + OFF_IDX))[sl];
            } else {
                w  = weights[s];
                a0 = albedos[s * 3 + 0];
                a1 = albedos[s * 3 + 1];
                a2 = albedos[s * 3 + 2];
                if (is64) r = (int)((const long long*)ray_idx)[s];
                else      r = ((const int*)ray_idx)[s];
            }
        }

        // all stage reads done -> release stage (one arrive per warp)
        __syncwarp();
        if (lane == 0)
            asm volatile("mbarrier.arrive.release.cta.shared::cta.b64 _, [%0];"
                         :: "r"(smem_u32(&sm_empty[stage])) : "memory");

        float t0f = fmaf(nx, d0.x, fmaf(ny, d0.y, nz * d0.z));
        float t1f = fmaf(nx, d0.w, fmaf(ny, d1.x, nz * d1.y));
        float t2f = fmaf(nx, d1.z, fmaf(ny, d1.w, nz * d2.x));
        float t3f = fmaf(nx, d2.y, fmaf(ny, d2.z, nz * d2.w));

        int cnt = (t0f > 0.f) + (t1f > 0.f) + (t2f > 0.f) + (t3f > 0.f);

        t0f = fminf(fmaxf(t0f, 0.f), 1.f) * v.x;
        t1f = fminf(fmaxf(t1f, 0.f), 1.f) * v.y;
        t2f = fminf(fmaxf(t2f, 0.f), 1.f) * v.z;
        t3f = fminf(fmaxf(t3f, 0.f), 1.f) * v.w;

        float s0 = fmaf(t0f, c0.x, fmaf(t1f, c0.w, fmaf(t2f, c1.z, t3f * c2.y)));
        float s1 = fmaf(t0f, c0.y, fmaf(t1f, c1.x, fmaf(t2f, c1.w, t3f * c2.z)));
        float s2 = fmaf(t0f, c0.z, fmaf(t1f, c1.y, fmaf(t2f, c2.x, t3f * c2.w)));

        #pragma unroll
        for (int off = 8; off; off >>= 1) {
            s0  += __shfl_xor_sync(0xFFFFFFFFu, s0,  off);
            s1  += __shfl_xor_sync(0xFFFFFFFFu, s1,  off);
            s2  += __shfl_xor_sync(0xFFFFFFFFu, s2,  off);
            cnt += __shfl_xor_sync(0xFFFFFFFFu, cnt, off);
        }

        if (sub == 0 && live) {
            float c   = (cnt > 0) ? (float)cnt : 1.0f;
            float inv = 1.0f / c;
            atomicAdd(&g_acc[r * 4 + 0], w * a0 * s0 * inv);
            atomicAdd(&g_acc[r * 4 + 1], w * a1 * s1 * inv);
            atomicAdd(&g_acc[r * 4 + 2], w * a2 * s2 * inv);
            atomicAdd(&g_acc[r * 4 + 3], w);
        }

        if (++stage == NSTAGE) { stage = 0; phase ^= 1; }
    }
}

// finalize: blend + sRGB, then zero g_acc for the NEXT call.
__global__ void finalize_kernel(const float* __restrict__ bg,
                                float* __restrict__ out, int R) {
    int r = blockIdx.x * blockDim.x + threadIdx.x;
    if (r >= R) return;
    float aw = g_acc[r * 4 + 3];
    float x0 = g_acc[r * 4 + 0];
    float x1 = g_acc[r * 4 + 1];
    float x2 = g_acc[r * 4 + 2];
    float one_m = 1.0f - aw;
    float xr[3] = { x0 + bg[r * 3 + 0] * one_m,
                    x1 + bg[r * 3 + 1] * one_m,
                    x2 + bg[r * 3 + 2] * one_m };
    #pragma unroll
    for (int c = 0; c < 3; ++c) {
        float x = xr[c];
        float safe = fmaxf(x, 1e-8f);
        float y = (x <= 0.0031308f) ? (12.92f * x)
                                    : (1.055f * __powf(safe, 1.0f / 2.4f) - 0.055f);
        out[r * 3 + c] = y;
    }
    g_acc[r * 4 + 0] = 0.0f;
    g_acc[r * 4 + 1] = 0.0f;
    g_acc[r * 4 + 2] = 0.0f;
    g_acc[r * 4 + 3] = 0.0f;
}

// Fallback for L != 64
__global__ void shade_kernel_generic(
        const float* __restrict__ albedos,
        const float* __restrict__ normals,
        const float* __restrict__ ldir,
        const float* __restrict__ lcol,
        const float* __restrict__ vis,
        const float* __restrict__ weights,
        const void*  __restrict__ ray_idx,
        int N, int L) {
    int gwarp = (blockIdx.x * blockDim.x + threadIdx.x) >> 5;
    int lane  = threadIdx.x & 31;
    if (gwarp >= N) return;
    float nx = normals[gwarp * 3 + 0];
    float ny = normals[gwarp * 3 + 1];
    float nz = normals[gwarp * 3 + 2];
    const float* ldp = ldir + (size_t)gwarp * L * 3;
    const float* lcp = lcol + (size_t)gwarp * L * 3;
    const float* vp  = vis  + (size_t)gwarp * L;
    float s0 = 0.f, s1 = 0.f, s2 = 0.f;
    int cnt = 0;
    for (int j = lane; j < L; j += 32) {
        float dx = ldp[j * 3 + 0], dy = ldp[j * 3 + 1], dz = ldp[j * 3 + 2];
        float d  = fmaf(nx, dx, fmaf(ny, dy, nz * dz));
        cnt += (d > 0.f) ? 1 : 0;
        d = fminf(fmaxf(d, 0.f), 1.f);
        float dv = d * vp[j];
        s0 = fmaf(dv, lcp[j * 3 + 0], s0);
        s1 = fmaf(dv, lcp[j * 3 + 1], s1);
        s2 = fmaf(dv, lcp[j * 3 + 2], s2);
    }
    #pragma unroll
    for (int off = 16; off; off >>= 1) {
        s0  += __shfl_xor_sync(0xFFFFFFFFu, s0,  off);
        s1  += __shfl_xor_sync(0xFFFFFFFFu, s1,  off);
        s2  += __shfl_xor_sync(0xFFFFFFFFu, s2,  off);
        cnt += __shfl_xor_sync(0xFFFFFFFFu, cnt, off);
    }
    if (lane == 0) {
        float c   = (cnt > 0) ? (float)cnt : 1.0f;
        float inv = 1.0f / c;
        float w   = weights[gwarp];
        int r;
        if (g_idx_is64) r = (int)((const long long*)ray_idx)[gwarp];
        else            r = ((const int*)ray_idx)[gwarp];
        atomicAdd(&g_acc[r * 4 + 0], w * albedos[gwarp * 3 + 0] * s0 * inv);
        atomicAdd(&g_acc[r * 4 + 1], w * albedos[gwarp * 3 + 1] * s1 * inv);
        atomicAdd(&g_acc[r * 4 + 2], w * albedos[gwarp * 3 + 2] * s2 * inv);
        atomicAdd(&g_acc[r * 4 + 3], w);
    }
}

extern "C" void kernel_launch(void* const* d_in, const int* in_sizes, int n_in,
                              void* d_out, int out_size) {
    const float* albedos = (const float*)d_in[0];
    const float* normals = (const float*)d_in[1];
    const float* ldir    = (const float*)d_in[2];
    const float* lcol    = (const float*)d_in[3];
    const float* vis     = (const float*)d_in[4];
    const float* bg      = (const float*)d_in[5];
    const float* weights = (const float*)d_in[6];
    const void*  ray_idx = (const void*) d_in[7];
    float* out = (float*)d_out;

    int N = in_sizes[0] / 3;
    int L = (N > 0) ? in_sizes[2] / (N * 3) : 1;
    int R = out_size / 3;
    if (R > MAX_RAYS) R = MAX_RAYS;

    // g_acc zero at load (call 1); finalize re-zeros it each call.
    detect_idx_kernel<<<1, 1024>>>((const int*)ray_idx, in_sizes[7]);

    if (L == 64) {
        static int smem_set = 0;
        if (!smem_set) {
            cudaFuncSetAttribute(shade_pipe_kernel,
                                 cudaFuncAttributeMaxDynamicSharedMemorySize,
                                 SMEM_BYTES);
            smem_set = 1;
        }
        int ntiles = (N + SPB - 1) / SPB;
        int grid = 148;                 // 1 CTA per SM
        if (grid > ntiles) grid = ntiles;
        shade_pipe_kernel<<<grid, 544, SMEM_BYTES>>>(
            albedos, normals, ldir, lcol, vis, weights, ray_idx, N, ntiles);
    } else {
        int blocks = (N + 7) / 8;
        shade_kernel_generic<<<blocks, 256>>>(
            albedos, normals, ldir, lcol, vis, weights, ray_idx, N, L);
    }

    finalize_kernel<<<(R + 255) / 256, 256>>>(bg, out, R);
}

// round 17
// speedup vs baseline: 1.2189x; 1.0154x over previous
#include <cuda_runtime.h>
#include <cuda_bf16.h>
#include <cstdint>

// ---------------------------------------------------------------------------
// RGBLambertianRendererWithVisibility — FINAL (measured best: 152.0us)
//   Persistent TMA pipeline: SPB=32, NSTAGE=3 (175KB smem), 1 CTA/SM,
//   warp-specialized producer, full-TMA staging of ALL per-sample data,
//   contiguous per-CTA tile partition, __powf finalize(+zero).
//   Launches: [detect, shade, finalize].
// ---------------------------------------------------------------------------

#define MAX_RAYS 65536
#define SPB 32
#define NSTAGE 3
#define NCW 16                         // compute warps
// stage layout (floats)
#define OFF_DIR  0
#define OFF_COL  (SPB * 192)
#define OFF_VIS  (SPB * 384)
#define OFF_NRM  (OFF_VIS + SPB * 64)
#define OFF_ALB  (OFF_NRM + SPB * 3)
#define OFF_WGT  (OFF_ALB + SPB * 3)
#define OFF_IDX  (OFF_WGT + SPB)
#define STAGE_FLOATS (OFF_IDX + SPB * 2)        // 14624 floats = 58496 B
#define SMEM_BYTES (NSTAGE * STAGE_FLOATS * 4)  // 175488 B

__device__ float g_acc[MAX_RAYS * 4];
__device__ int   g_idx_is64;

// int32 vs int64 ray_indices: inspect last 2048 of the first N int32 words
// (in-bounds for both layouts). Sorted nonneg indices are nonzero there for
// int32; int64 interleaves zero high words.
__global__ void detect_idx_kernel(const int* __restrict__ words, int n_words_safe) {
    int end   = n_words_safe;
    int start = end - 2048; if (start < 0) start = 0;
    int z = 0;
    for (int i = start + threadIdx.x; i < end; i += blockDim.x)
        z |= (words[i] == 0);
    int any = __syncthreads_or(z);
    if (threadIdx.x == 0) g_idx_is64 = any ? 1 : 0;
}

__device__ __forceinline__ uint32_t smem_u32(const void* p) {
    uint32_t a;
    asm("{ .reg .u64 t; cvta.to.shared.u64 t, %1; cvt.u32.u64 %0, t; }"
        : "=r"(a) : "l"(p));
    return a;
}

__device__ __forceinline__ void mbar_wait(uint32_t mbar, uint32_t parity) {
    uint32_t done;
    asm volatile(
        "{\n\t"
        ".reg .pred p;\n\t"
        "mbarrier.try_wait.parity.acquire.cta.shared::cta.b64 p, [%1], %2;\n\t"
        "selp.b32 %0, 1, 0, p;\n\t"
        "}" : "=r"(done) : "r"(mbar), "r"(parity) : "memory");
    if (!done) {
        asm volatile(
            "{\n\t"
            ".reg .pred P1;\n\t"
            "WAIT_LOOP_%=:\n\t"
            "mbarrier.try_wait.parity.acquire.cta.shared::cta.b64 P1, [%0], %1, 0x989680;\n\t"
            "@P1 bra.uni WAIT_DONE_%=;\n\t"
            "bra.uni WAIT_LOOP_%=;\n\t"
            "WAIT_DONE_%=:\n\t"
            "}" :: "r"(mbar), "r"(parity) : "memory");
    }
}

__device__ __forceinline__ void bulk_cp(uint32_t dst, const void* src,
                                        unsigned bytes, uint32_t mbar) {
    asm volatile(
        "cp.async.bulk.shared::cta.global.mbarrier::complete_tx::bytes [%0], [%1], %2, [%3];"
        :: "r"(dst), "l"(src), "r"(bytes), "r"(mbar) : "memory");
}

// --- persistent pipelined shade (L == 64) -----------------------------------
__global__ __launch_bounds__(544) void shade_pipe_kernel(
        const float* __restrict__ albedos,
        const float* __restrict__ normals,
        const float* __restrict__ ldir,
        const float* __restrict__ lcol,
        const float* __restrict__ vis,
        const float* __restrict__ weights,
        const void*  __restrict__ ray_idx,
        int N, int ntiles) {
    extern __shared__ __align__(16) float smem[];
    __shared__ __align__(8) unsigned long long sm_full[NSTAGE];
    __shared__ __align__(8) unsigned long long sm_empty[NSTAGE];

    int tid  = threadIdx.x;
    int warp = tid >> 5;
    int lane = tid & 31;

    if (tid == 0) {
        #pragma unroll
        for (int s = 0; s < NSTAGE; ++s) {
            asm volatile("mbarrier.init.shared.b64 [%0], 1;"
                         :: "r"(smem_u32(&sm_full[s])) : "memory");
            asm volatile("mbarrier.init.shared.b64 [%0], %1;"
                         :: "r"(smem_u32(&sm_empty[s])), "r"(NCW) : "memory");
        }
    }
    __syncthreads();

    // contiguous tile partition: CTA b owns tiles [t0, t0+cnt)
    int nb   = (int)gridDim.x;
    int bpc  = ntiles / nb;            // base tiles per CTA
    int rem  = ntiles - bpc * nb;      // first `rem` CTAs get one extra
    int b    = (int)blockIdx.x;
    int t0   = b * bpc + (b < rem ? b : rem);
    int my_tiles = bpc + (b < rem ? 1 : 0);
    if (my_tiles == 0) return;

    int is64 = g_idx_is64;

    if (warp == NCW) {
        // ---------------- producer warp ----------------
        if (lane == 0) {
            int stage = 0, phase = 1;
            for (int j = 0; j < my_tiles; ++j) {
                mbar_wait(smem_u32(&sm_empty[stage]), (uint32_t)phase);
                asm volatile("fence.proxy.async.shared::cta;" ::: "memory");
                int tb = (t0 + j) * SPB;
                int nloc = N - tb; if (nloc > SPB) nloc = SPB;
                bool aux = (nloc % 4) == 0;

                float* stg = smem + stage * STAGE_FLOATS;
                uint32_t mb = smem_u32(&sm_full[stage]);
                unsigned db = (unsigned)nloc * 768u;
                unsigned vb = (unsigned)nloc * 256u;
                unsigned ab = aux ? ((unsigned)nloc * (12u + 12u + 4u)
                                     + (unsigned)nloc * (is64 ? 8u : 4u)) : 0u;
                asm volatile("mbarrier.arrive.expect_tx.shared.b64 _, [%0], %1;"
                             :: "r"(mb), "r"(db * 2u + vb + ab) : "memory");
                bulk_cp(smem_u32(stg + OFF_DIR), ldir + (size_t)tb * 192, db, mb);
                bulk_cp(smem_u32(stg + OFF_COL), lcol + (size_t)tb * 192, db, mb);
                bulk_cp(smem_u32(stg + OFF_VIS), vis  + (size_t)tb * 64,  vb, mb);
                if (aux) {
                    bulk_cp(smem_u32(stg + OFF_NRM), normals + (size_t)tb * 3,
                            (unsigned)nloc * 12u, mb);
                    bulk_cp(smem_u32(stg + OFF_ALB), albedos + (size_t)tb * 3,
                            (unsigned)nloc * 12u, mb);
                    bulk_cp(smem_u32(stg + OFF_WGT), weights + (size_t)tb,
                            (unsigned)nloc * 4u, mb);
                    if (is64)
                        bulk_cp(smem_u32(stg + OFF_IDX),
                                (const long long*)ray_idx + tb,
                                (unsigned)nloc * 8u, mb);
                    else
                        bulk_cp(smem_u32(stg + OFF_IDX),
                                (const int*)ray_idx + tb,
                                (unsigned)nloc * 4u, mb);
                }
                if (++stage == NSTAGE) { stage = 0; phase ^= 1; }
            }
        }
        return;
    }

    // ---------------- compute warps (warp 0..15) ----------------
    int half = lane >> 4;
    int sub  = lane & 15;
    int sl   = warp * 2 + half;        // local sample 0..31

    int stage = 0, phase = 0;
    for (int j = 0; j < my_tiles; ++j) {
        int base = (t0 + j) * SPB;
        int nloc = N - base; if (nloc > SPB) nloc = SPB;
        bool aux = (nloc % 4) == 0;

        mbar_wait(smem_u32(&sm_full[stage]), (uint32_t)phase);

        float* stg = smem + stage * STAGE_FLOATS;
        int s    = base + sl;
        bool live = (s < N);
        int sll  = live ? sl : 0;

        const float4* sd = (const float4*)(stg + OFF_DIR + sll * 192);
        const float4* sc = (const float4*)(stg + OFF_COL + sll * 192);
        const float4* sv = (const float4*)(stg + OFF_VIS + sll * 64);

        float4 d0 = sd[sub * 3 + 0];
        float4 d1 = sd[sub * 3 + 1];
        float4 d2 = sd[sub * 3 + 2];
        float4 c0 = sc[sub * 3 + 0];
        float4 c1 = sc[sub * 3 + 1];
        float4 c2 = sc[sub * 3 + 2];
        float4 v  = sv[sub];

        float nx, ny, nz;
        if (aux) {
            nx = stg[OFF_NRM + sll * 3 + 0];
            ny = stg[OFF_NRM + sll * 3 + 1];
            nz = stg[OFF_NRM + sll * 3 + 2];
        } else {
            int scl = live ? s : 0;
            nx = normals[scl * 3 + 0];
            ny = normals[scl * 3 + 1];
            nz = normals[scl * 3 + 2];
        }

        float w = 0.f, a0 = 0.f, a1 = 0.f, a2 = 0.f;
        int r = 0;
        if (sub == 0 && live) {
            if (aux) {
                w  = stg[OFF_WGT + sl];
                a0 = stg[OFF_ALB + sl * 3 + 0];
                a1 = stg[OFF_ALB + sl * 3 + 1];
                a2 = stg[OFF_ALB + sl * 3 + 2];
                if (is64) r = (int)((const long long*)(stg + OFF_IDX))[sl];
                else      r = ((const int*)(stg + OFF_IDX))[sl];
            } else {
                w  = weights[s];
                a0 = albedos[s * 3 + 0];
                a1 = albedos[s * 3 + 1];
                a2 = albedos[s * 3 + 2];
                if (is64) r = (int)((const long long*)ray_idx)[s];
                else      r = ((const int*)ray_idx)[s];
            }
        }

        // all stage reads done -> release stage (one arrive per warp)
        __syncwarp();
        if (lane == 0)
            asm volatile("mbarrier.arrive.release.cta.shared::cta.b64 _, [%0];"
                         :: "r"(smem_u32(&sm_empty[stage])) : "memory");

        float t0f = fmaf(nx, d0.x, fmaf(ny, d0.y, nz * d0.z));
        float t1f = fmaf(nx, d0.w, fmaf(ny, d1.x, nz * d1.y));
        float t2f = fmaf(nx, d1.z, fmaf(ny, d1.w, nz * d2.x));
        float t3f = fmaf(nx, d2.y, fmaf(ny, d2.z, nz * d2.w));

        int cnt = (t0f > 0.f) + (t1f > 0.f) + (t2f > 0.f) + (t3f > 0.f);

        t0f = fminf(fmaxf(t0f, 0.f), 1.f) * v.x;
        t1f = fminf(fmaxf(t1f, 0.f), 1.f) * v.y;
        t2f = fminf(fmaxf(t2f, 0.f), 1.f) * v.z;
        t3f = fminf(fmaxf(t3f, 0.f), 1.f) * v.w;

        float s0 = fmaf(t0f, c0.x, fmaf(t1f, c0.w, fmaf(t2f, c1.z, t3f * c2.y)));
        float s1 = fmaf(t0f, c0.y, fmaf(t1f, c1.x, fmaf(t2f, c1.w, t3f * c2.z)));
        float s2 = fmaf(t0f, c0.z, fmaf(t1f, c1.y, fmaf(t2f, c2.x, t3f * c2.w)));

        #pragma unroll
        for (int off = 8; off; off >>= 1) {
            s0  += __shfl_xor_sync(0xFFFFFFFFu, s0,  off);
            s1  += __shfl_xor_sync(0xFFFFFFFFu, s1,  off);
            s2  += __shfl_xor_sync(0xFFFFFFFFu, s2,  off);
            cnt += __shfl_xor_sync(0xFFFFFFFFu, cnt, off);
        }

        if (sub == 0 && live) {
            float c   = (cnt > 0) ? (float)cnt : 1.0f;
            float inv = 1.0f / c;
            atomicAdd(&g_acc[r * 4 + 0], w * a0 * s0 * inv);
            atomicAdd(&g_acc[r * 4 + 1], w * a1 * s1 * inv);
            atomicAdd(&g_acc[r * 4 + 2], w * a2 * s2 * inv);
            atomicAdd(&g_acc[r * 4 + 3], w);
        }

        if (++stage == NSTAGE) { stage = 0; phase ^= 1; }
    }
}

// finalize: blend + sRGB, then zero g_acc for the NEXT call.
__global__ void finalize_kernel(const float* __restrict__ bg,
                                float* __restrict__ out, int R) {
    int r = blockIdx.x * blockDim.x + threadIdx.x;
    if (r >= R) return;
    float aw = g_acc[r * 4 + 3];
    float x0 = g_acc[r * 4 + 0];
    float x1 = g_acc[r * 4 + 1];
    float x2 = g_acc[r * 4 + 2];
    float one_m = 1.0f - aw;
    float xr[3] = { x0 + bg[r * 3 + 0] * one_m,
                    x1 + bg[r * 3 + 1] * one_m,
                    x2 + bg[r * 3 + 2] * one_m };
    #pragma unroll
    for (int c = 0; c < 3; ++c) {
        float x = xr[c];
        float safe = fmaxf(x, 1e-8f);
        float y = (x <= 0.0031308f) ? (12.92f * x)
                                    : (1.055f * __powf(safe, 1.0f / 2.4f) - 0.055f);
        out[r * 3 + c] = y;
    }
    g_acc[r * 4 + 0] = 0.0f;
    g_acc[r * 4 + 1] = 0.0f;
    g_acc[r * 4 + 2] = 0.0f;
    g_acc[r * 4 + 3] = 0.0f;
}

// Fallback for L != 64
__global__ void shade_kernel_generic(
        const float* __restrict__ albedos,
        const float* __restrict__ normals,
        const float* __restrict__ ldir,
        const float* __restrict__ lcol,
        const float* __restrict__ vis,
        const float* __restrict__ weights,
        const void*  __restrict__ ray_idx,
        int N, int L) {
    int gwarp = (blockIdx.x * blockDim.x + threadIdx.x) >> 5;
    int lane  = threadIdx.x & 31;
    if (gwarp >= N) return;
    float nx = normals[gwarp * 3 + 0];
    float ny = normals[gwarp * 3 + 1];
    float nz = normals[gwarp * 3 + 2];
    const float* ldp = ldir + (size_t)gwarp * L * 3;
    const float* lcp = lcol + (size_t)gwarp * L * 3;
    const float* vp  = vis  + (size_t)gwarp * L;
    float s0 = 0.f, s1 = 0.f, s2 = 0.f;
    int cnt = 0;
    for (int j = lane; j < L; j += 32) {
        float dx = ldp[j * 3 + 0], dy = ldp[j * 3 + 1], dz = ldp[j * 3 + 2];
        float d  = fmaf(nx, dx, fmaf(ny, dy, nz * dz));
        cnt += (d > 0.f) ? 1 : 0;
        d = fminf(fmaxf(d, 0.f), 1.f);
        float dv = d * vp[j];
        s0 = fmaf(dv, lcp[j * 3 + 0], s0);
        s1 = fmaf(dv, lcp[j * 3 + 1], s1);
        s2 = fmaf(dv, lcp[j * 3 + 2], s2);
    }
    #pragma unroll
    for (int off = 16; off; off >>= 1) {
        s0  += __shfl_xor_sync(0xFFFFFFFFu, s0,  off);
        s1  += __shfl_xor_sync(0xFFFFFFFFu, s1,  off);
        s2  += __shfl_xor_sync(0xFFFFFFFFu, s2,  off);
        cnt += __shfl_xor_sync(0xFFFFFFFFu, cnt, off);
    }
    if (lane == 0) {
        float c   = (cnt > 0) ? (float)cnt : 1.0f;
        float inv = 1.0f / c;
        float w   = weights[gwarp];
        int r;
        if (g_idx_is64) r = (int)((const long long*)ray_idx)[gwarp];
        else            r = ((const int*)ray_idx)[gwarp];
        atomicAdd(&g_acc[r * 4 + 0], w * albedos[gwarp * 3 + 0] * s0 * inv);
        atomicAdd(&g_acc[r * 4 + 1], w * albedos[gwarp * 3 + 1] * s1 * inv);
        atomicAdd(&g_acc[r * 4 + 2], w * albedos[gwarp * 3 + 2] * s2 * inv);
        atomicAdd(&g_acc[r * 4 + 3], w);
    }
}

extern "C" void kernel_launch(void* const* d_in, const int* in_sizes, int n_in,
                              void* d_out, int out_size) {
    const float* albedos = (const float*)d_in[0];
    const float* normals = (const float*)d_in[1];
    const float* ldir    = (const float*)d_in[2];
    const float* lcol    = (const float*)d_in[3];
    const float* vis     = (const float*)d_in[4];
    const float* bg      = (const float*)d_in[5];
    const float* weights = (const float*)d_in[6];
    const void*  ray_idx = (const void*) d_in[7];
    float* out = (float*)d_out;

    int N = in_sizes[0] / 3;
    int L = (N > 0) ? in_sizes[2] / (N * 3) : 1;
    int R = out_size / 3;
    if (R > MAX_RAYS) R = MAX_RAYS;

    // g_acc zero at load (call 1); finalize re-zeros it each call.
    detect_idx_kernel<<<1, 1024>>>((const int*)ray_idx, in_sizes[7]);

    if (L == 64) {
        static int smem_set = 0;
        if (!smem_set) {
            cudaFuncSetAttribute(shade_pipe_kernel,
                                 cudaFuncAttributeMaxDynamicSharedMemorySize,
                                 SMEM_BYTES);
            smem_set = 1;
        }
        int ntiles = (N + SPB - 1) / SPB;
        int grid = 148;                 // 1 CTA per SM
        if (grid > ntiles) grid = ntiles;
        shade_pipe_kernel<<<grid, 544, SMEM_BYTES>>>(
            albedos, normals, ldir, lcol, vis, weights, ray_idx, N, ntiles);
    } else {
        int blocks = (N + 7) / 8;
        shade_kernel_generic<<<blocks, 256>>>(
            albedos, normals, ldir, lcol, vis, weights, ray_idx, N, L);
    }

    finalize_kernel<<<(R + 255) / 256, 256>>>(bg, out, R);
}